// round 10
// baseline (speedup 1.0000x reference)
#include <cuda_runtime.h>

// 2-layer LSTM (B=2048, T=1000, I=13, H=32) + Linear(32)->ReLU->Linear(3).
// 148 blocks x 256 threads. Block = two independent 7-batch halves.
// Half = L0 group (64 thr) + L1 group (64 thr).
// Dataflow (as R8): layer-1's h0-consuming GEMM is split - row gl computed by
// the L0 group right after it produces h0 (px buffer), row gl+64 by the L1
// group. L1's big Wh1*h1 GEMM is group-private, so only the px/h0 tail
// crosses groups.
// NEW vs R8 (deadlock fix): cross-group barriers idA/idB are PARITY-SPLIT
// (indexed by t&1). With a single barrier, L1's arrivals at t=0 and t=1 both
// landed before L0's first wait (t=2), summing to 128 and self-releasing
// with no waiters - losing the lag credits and deadlocking. With per-parity
// barriers, arrive/wait rounds strictly alternate (proved by the cross-chain
// ordering), and counts are balanced exactly via the t+2<TT arrive guard.

#define BB    2048
#define TT    1000
#define II    13
#define HH    32
#define NC    3
#define NBH   7            // batches per half
#define BPB   14
#define GRIDN 148
#define GSTR  9            // gate smem row stride (coprime with 32 banks)

typedef unsigned long long ull;

struct alignas(16) Smem {
    float xs[2][2][NBH][16];        // [half][parity][b][k], k padded 13->16
    float h0[2][2][NBH][HH];        // [half][parity][b][k] (cross-group read)
    float h1[2][NBH][HH];           // [half][b][k] (L1-group private)
    float gates[2][2][128 * GSTR];  // [half][phys-group][row*GSTR + b]
    float px[2][2][64 * GSTR];      // [half][parity][row(0..63)*GSTR + b]
};

__device__ __forceinline__ ull ffma2(ull a, ull b, ull c) {
    ull d;
    asm("fma.rn.f32x2 %0, %1, %2, %3;" : "=l"(d) : "l"(a), "l"(b), "l"(c));
    return d;
}
__device__ __forceinline__ ull packf2(float lo, float hi) {
    ull r;
    asm("mov.b64 %0, {%1, %2};" : "=l"(r) : "f"(lo), "f"(hi));
    return r;
}
__device__ __forceinline__ float hadd2(ull a) {
    float lo, hi;
    asm("mov.b64 {%0, %1}, %2;" : "=f"(lo), "=f"(hi) : "l"(a));
    return lo + hi;
}
__device__ __forceinline__ ull d2l(double d) { return __double_as_longlong(d); }

__device__ __forceinline__ float tanhap(float v) {
    float y;
    asm("tanh.approx.f32 %0, %1;" : "=f"(y) : "f"(v));
    return y;
}
__device__ __forceinline__ float sigf(float v) {
    return fmaf(tanhap(0.5f * v), 0.5f, 0.5f);
}

// 2-row GEMM: acc[i][b] += v-pairs * w{i}-pairs
template <int NC4, int BSTR, int NW>
__device__ __forceinline__ void gemm2(ull (&acc)[2][NBH], const float* __restrict__ vb,
                                      const ull (&w0)[NW], const ull (&w1)[NW]) {
#pragma unroll
    for (int c = 0; c < NC4; c++) {
#pragma unroll
        for (int b = 0; b < NBH; b++) {
            double2 v = *reinterpret_cast<const double2*>(vb + b * BSTR + c * 4);
            ull vx = d2l(v.x), vy = d2l(v.y);
            acc[0][b] = ffma2(vx, w0[2 * c],     acc[0][b]);
            acc[0][b] = ffma2(vy, w0[2 * c + 1], acc[0][b]);
            acc[1][b] = ffma2(vx, w1[2 * c],     acc[1][b]);
            acc[1][b] = ffma2(vy, w1[2 * c + 1], acc[1][b]);
        }
    }
}
// 1-row GEMM
template <int NC4, int BSTR>
__device__ __forceinline__ void gemm1(ull (&acc)[NBH], const float* __restrict__ vb,
                                      const ull (&w)[16]) {
#pragma unroll
    for (int c = 0; c < NC4; c++) {
#pragma unroll
        for (int b = 0; b < NBH; b++) {
            double2 v = *reinterpret_cast<const double2*>(vb + b * BSTR + c * 4);
            acc[b] = ffma2(d2l(v.x), w[2 * c],     acc[b]);
            acc[b] = ffma2(d2l(v.y), w[2 * c + 1], acc[b]);
        }
    }
}

__global__ void __launch_bounds__(256, 1)
lstm_fused_kernel(const float* __restrict__ x,
                  const float* __restrict__ Wih0, const float* __restrict__ Whh0,
                  const float* __restrict__ bih0, const float* __restrict__ bhh0,
                  const float* __restrict__ Wih1, const float* __restrict__ Whh1,
                  const float* __restrict__ bih1, const float* __restrict__ bhh1,
                  const float* __restrict__ Wc1,  const float* __restrict__ bc1,
                  const float* __restrict__ Wc2,  const float* __restrict__ bc2,
                  float* __restrict__ out) {
    extern __shared__ char smem_raw[];
    Smem& s = *reinterpret_cast<Smem*>(smem_raw);
    const int tid  = threadIdx.x;
    const int half = tid >> 7;
    const int lt   = tid & 127;
    const int grp  = lt >> 6;
    const int gl   = lt & 63;
    const bool is_l0 = ((grp ^ half) == 0);   // SMSP-balanced layer map
    const int bbase = blockIdx.x * BPB + half * NBH;

    // ---- zero state (xs, h0, h1 contiguous at struct start) ----
    {
        float* zp = reinterpret_cast<float*>(&s);
        const int zn = (int)((sizeof(s.xs) + sizeof(s.h0) + sizeof(s.h1)) / 4);
        for (int i = tid; i < zn; i += 256) zp[i] = 0.0f;
    }
    // ---- stage x(0) (batch-clamped for tail blocks) ----
    for (int i = tid; i < 2 * NBH * II; i += 256) {
        int hf = i / (NBH * II), r = i % (NBH * II), b = r / II, k = r % II;
        int gb = blockIdx.x * BPB + hf * NBH + b;
        if (gb > BB - 1) gb = BB - 1;
        s.xs[hf][0][b][k] = x[(size_t)gb * TT * II + k];
    }

    // ---- register-resident weights ----
    // L0: wA=Wih0 (2 rows, 8 pairs used), wB=Whh0 (2 rows), wX=Wih1 row gl
    // L1: wA=Whh1 (2 rows), wX=Wih1 row gl+64 (wB unused)
    ull wA[2][16], wB[2][16], wX[16];
    ull biasA, biasB, biasX;
    if (is_l0) {
#pragma unroll
        for (int i = 0; i < 2; i++) {
            int r = gl + i * 64;
#pragma unroll
            for (int p = 0; p < 8; p++) {
                float lo = (2 * p     < II) ? Wih0[r * II + 2 * p]     : 0.0f;
                float hi = (2 * p + 1 < II) ? Wih0[r * II + 2 * p + 1] : 0.0f;
                wA[i][p] = packf2(lo, hi);
            }
#pragma unroll
            for (int p = 8; p < 16; p++) wA[i][p] = 0;
#pragma unroll
            for (int p = 0; p < 16; p++)
                wB[i][p] = packf2(Whh0[r * HH + 2 * p], Whh0[r * HH + 2 * p + 1]);
        }
#pragma unroll
        for (int p = 0; p < 16; p++)
            wX[p] = packf2(Wih1[gl * HH + 2 * p], Wih1[gl * HH + 2 * p + 1]);
        biasA = packf2(bih0[gl] + bhh0[gl], 0.0f);
        biasB = packf2(bih0[gl + 64] + bhh0[gl + 64], 0.0f);
        biasX = packf2(bih1[gl] + bhh1[gl], 0.0f);
    } else {
#pragma unroll
        for (int i = 0; i < 2; i++) {
            int r = gl + i * 64;
#pragma unroll
            for (int p = 0; p < 16; p++) {
                wA[i][p] = packf2(Whh1[r * HH + 2 * p], Whh1[r * HH + 2 * p + 1]);
                wB[i][p] = 0;
            }
        }
        int r1 = gl + 64;
#pragma unroll
        for (int p = 0; p < 16; p++)
            wX[p] = packf2(Wih1[r1 * HH + 2 * p], Wih1[r1 * HH + 2 * p + 1]);
        biasA = 0; biasB = 0;
        biasX = packf2(bih1[r1] + bhh1[r1], 0.0f);
    }

    // ---- elementwise map: unit eu, batch base ebb ----
    const int eu  = gl & 31;
    const int ebb = (gl >> 5) * 4;
    float cst[4] = {0.f, 0.f, 0.f, 0.f};

    float* gs = s.gates[half][grp];

    // ---- x staging slots (L0 threads) ----
    const int pb0 = gl >> 4,        pk0 = gl & 15;
    const int pb1 = (gl + 64) >> 4, pk1 = (gl + 64) & 15;
    const bool pv0 = (pb0 < NBH) && (pk0 < II);
    const bool pv1 = (pb1 < NBH) && (pk1 < II);
    int cb0 = bbase + pb0; if (cb0 > BB - 1) cb0 = BB - 1;
    int cb1 = bbase + pb1; if (cb1 > BB - 1) cb1 = BB - 1;
    const float* xc0 = x + (size_t)cb0 * TT * II + pk0;
    const float* xc1 = x + (size_t)cb1 * TT * II + pk1;

    // barrier ids: idA[p] = 1+4h+p, idB[p] = 3+4h+p, GBAR = 9+2h+grp
    const int idA0 = 1 + 4 * half;
    const int idB0 = 3 + 4 * half;
    const int idG  = 9 + 2 * half + grp;

    __syncthreads();

#define ARRV(id) asm volatile("bar.arrive %0, 128;" :: "r"(id) : "memory")
#define WAIT(id) asm volatile("bar.sync %0, 128;"   :: "r"(id) : "memory")
#define GBAR()   asm volatile("bar.sync %0, 64;"    :: "r"(idG) : "memory")

    for (int t = 0; t < TT; t++) {
        const int par = t & 1;
        if (is_l0) {
            // ---- GEMM0: gates0(t) = b0 + Wx0*x(t) + Wh0*h0(t-1) ----
            const float* xsv = &s.xs[half][par][0][0];
            const float* h0v = &s.h0[half][par ^ 1][0][0];   // h0(t-1)
            ull acc[2][NBH];
#pragma unroll
            for (int b = 0; b < NBH; b++) { acc[0][b] = biasA; acc[1][b] = biasB; }
            gemm2<4, 16, 16>(acc, xsv, wA[0], wA[1]);
            gemm2<8, HH, 16>(acc, h0v, wB[0], wB[1]);
#pragma unroll
            for (int b = 0; b < NBH; b++) {
                gs[gl * GSTR + b]        = hadd2(acc[0][b]);
                gs[(gl + 64) * GSTR + b] = hadd2(acc[1][b]);
            }
            float xn0 = 0.f, xn1 = 0.f;
            if (t + 1 < TT) {
                if (pv0) xn0 = xc0[(size_t)(t + 1) * II];
                if (pv1) xn1 = xc1[(size_t)(t + 1) * II];
            }
            GBAR();                         // gates0 ready
            if (t >= 2) WAIT(idB0 + par);   // h0/px slot par free (L1 done t-2)
            // ---- EW layer0: writes h0(t) into slot par ----
#pragma unroll
            for (int j = 0; j < 4; j++) {
                int b = ebb + j;
                if (b < NBH) {
                    float gi = gs[(eu)      * GSTR + b];
                    float gf = gs[(eu + 32) * GSTR + b];
                    float gg = gs[(eu + 64) * GSTR + b];
                    float go = gs[(eu + 96) * GSTR + b];
                    float ig = sigf(gi), fg = sigf(gf);
                    float gv = tanhap(gg), og = sigf(go);
                    cst[j] = fmaf(fg, cst[j], ig * gv);
                    s.h0[half][par][b][eu] = og * tanhap(cst[j]);
                }
            }
            if (t + 1 < TT) {
                if (pv0) s.xs[half][par ^ 1][pb0][pk0] = xn0;
                if (pv1) s.xs[half][par ^ 1][pb1][pk1] = xn1;
            }
            GBAR();                         // h0(t) / xs(t+1) visible in-group
            // ---- px(t) = b1 + Wx1[row gl]*h0(t) ----
            {
                const float* h0n = &s.h0[half][par][0][0];
                ull acc1[NBH];
#pragma unroll
                for (int b = 0; b < NBH; b++) acc1[b] = biasX;
                gemm1<8, HH>(acc1, h0n, wX);
                float* pxp = &s.px[half][par][0];
#pragma unroll
                for (int b = 0; b < NBH; b++)
                    pxp[gl * GSTR + b] = hadd2(acc1[b]);
            }
            ARRV(idA0 + par);               // px(t) + h0(t) published
        } else {
            // ---- Wh1*h1(t-1): group-private, no cross wait ----
            const float* h1v = &s.h1[half][0][0];
            ull acc[2][NBH];
#pragma unroll
            for (int b = 0; b < NBH; b++) { acc[0][b] = 0; acc[1][b] = 0; }
            gemm2<8, HH, 16>(acc, h1v, wA[0], wA[1]);
            WAIT(idA0 + par);               // px(t) + h0(t) ready
            // ---- row gl+64 of Wx1*h0(t), then combine ----
            {
                const float* h0n = &s.h0[half][par][0][0];
                ull acc1[NBH];
#pragma unroll
                for (int b = 0; b < NBH; b++) acc1[b] = biasX;
                gemm1<8, HH>(acc1, h0n, wX);
                const float* pxp = &s.px[half][par][0];
#pragma unroll
                for (int b = 0; b < NBH; b++) {
                    gs[gl * GSTR + b]        = hadd2(acc[0][b]) + pxp[gl * GSTR + b];
                    gs[(gl + 64) * GSTR + b] = hadd2(acc[1][b]) + hadd2(acc1[b]);
                }
            }
            if (t + 2 < TT) ARRV(idB0 + par);   // slot consumed (balanced count)
            GBAR();                         // gates1 ready
            // ---- EW layer1: writes h1(t) ----
#pragma unroll
            for (int j = 0; j < 4; j++) {
                int b = ebb + j;
                if (b < NBH) {
                    float gi = gs[(eu)      * GSTR + b];
                    float gf = gs[(eu + 32) * GSTR + b];
                    float gg = gs[(eu + 64) * GSTR + b];
                    float go = gs[(eu + 96) * GSTR + b];
                    float ig = sigf(gi), fg = sigf(gf);
                    float gv = tanhap(gg), og = sigf(go);
                    cst[j] = fmaf(fg, cst[j], ig * gv);
                    s.h1[half][b][eu] = og * tanhap(cst[j]);
                }
            }
            GBAR();                         // h1(t) visible in-group
        }
    }
    __syncthreads();

    // ---- classifier head ----
    {
        int hj = lt & 31, hb = lt >> 5;
        float* hs = s.gates[half][0];
#pragma unroll
        for (int s2 = 0; s2 < 2; s2++) {
            int b = hb + 4 * s2;
            if (b < NBH) {
                float a = bc1[hj];
#pragma unroll
                for (int k = 0; k < HH; k++)
                    a = fmaf(s.h1[half][b][k], Wc1[hj * HH + k], a);
                hs[hj * GSTR + b] = fmaxf(a, 0.0f);
            }
        }
    }
    __syncthreads();
    if (lt < NBH * NC) {
        int b = lt / NC, c = lt - b * NC;
        if (bbase + b < BB) {
            float* hs = s.gates[half][0];
            float o = bc2[c];
#pragma unroll
            for (int j = 0; j < HH; j++)
                o = fmaf(hs[j * GSTR + b], Wc2[c * HH + j], o);
            out[(size_t)(bbase + b) * NC + c] = o;
        }
    }
#undef ARRV
#undef WAIT
#undef GBAR
}

extern "C" void kernel_launch(void* const* d_in, const int* in_sizes, int n_in,
                              void* d_out, int out_size) {
    const float* x    = (const float*)d_in[0];
    const float* Wih0 = (const float*)d_in[1];
    const float* Whh0 = (const float*)d_in[2];
    const float* bih0 = (const float*)d_in[3];
    const float* bhh0 = (const float*)d_in[4];
    const float* Wih1 = (const float*)d_in[5];
    const float* Whh1 = (const float*)d_in[6];
    const float* bih1 = (const float*)d_in[7];
    const float* bhh1 = (const float*)d_in[8];
    const float* Wc1  = (const float*)d_in[9];
    const float* bc1  = (const float*)d_in[10];
    const float* Wc2  = (const float*)d_in[11];
    const float* bc2  = (const float*)d_in[12];
    float* out = (float*)d_out;

    cudaFuncSetAttribute(lstm_fused_kernel,
                         cudaFuncAttributeMaxDynamicSharedMemorySize,
                         (int)sizeof(Smem));

    lstm_fused_kernel<<<GRIDN, 256, sizeof(Smem)>>>(
        x, Wih0, Whh0, bih0, bhh0, Wih1, Whh1, bih1, bhh1,
        Wc1, bc1, Wc2, bc2, out);
}

// round 11
// speedup vs baseline: 1.3313x; 1.3313x over previous
#include <cuda_runtime.h>

// 2-layer LSTM (B=2048, T=1000, I=13, H=32) + Linear(32)->ReLU->Linear(3).
// 148 blocks x 256 threads. Block = two independent 7-batch halves.
// Half = L0 group (64 thr, layer-0 rows) + L1 group (64 thr, layer-1 rows),
// pipelined one step apart over double-buffered h0. R6 dataflow, plus:
//  (1) L1's group-private Whh1*h1 GEMM moved BEFORE its cross-group wait, so
//      only the 224-FFMA2 Wih1*h0 part sits after the h0 handoff;
//  (2) L0's cross wait moved from step-top to just before EW (intra-group
//      GBAR handles step-top ordering), unblocking L0's GEMM0;
//  (3) idA/idB are parity-split (slot-tagged) -> race/deadlock-free by
//      construction (R6's single barriers relied on a timing margin).

#define BB    2048
#define TT    1000
#define II    13
#define HH    32
#define NC    3
#define NBH   7            // batches per half
#define BPB   14
#define GRIDN 148
#define GSTR  9            // gate smem row stride (coprime with 32 banks)

typedef unsigned long long ull;

struct alignas(16) Smem {
    float xs[2][2][NBH][16];        // [half][parity][b][k], k padded 13->16
    float h0[2][2][NBH][HH];        // [half][slot][b][k]
    float h1[2][NBH][HH];           // [half][b][k] (L1-group private)
    float gates[2][2][128 * GSTR];  // [half][phys-group][row*GSTR + b]
};

__device__ __forceinline__ ull ffma2(ull a, ull b, ull c) {
    ull d;
    asm("fma.rn.f32x2 %0, %1, %2, %3;" : "=l"(d) : "l"(a), "l"(b), "l"(c));
    return d;
}
__device__ __forceinline__ ull packf2(float lo, float hi) {
    ull r;
    asm("mov.b64 %0, {%1, %2};" : "=l"(r) : "f"(lo), "f"(hi));
    return r;
}
__device__ __forceinline__ float hadd2(ull a) {
    float lo, hi;
    asm("mov.b64 {%0, %1}, %2;" : "=f"(lo), "=f"(hi) : "l"(a));
    return lo + hi;
}
__device__ __forceinline__ ull d2l(double d) { return __double_as_longlong(d); }

__device__ __forceinline__ float tanhap(float v) {
    float y;
    asm("tanh.approx.f32 %0, %1;" : "=f"(y) : "f"(v));
    return y;
}
__device__ __forceinline__ float sigf(float v) {
    return fmaf(tanhap(0.5f * v), 0.5f, 0.5f);
}

// acc[i][b] += sum over NC4 float4-chunks: v-pairs * w{i}-pairs (f32x2).
template <int NC4, int BSTR>
__device__ __forceinline__ void gemm2(ull (&acc)[2][NBH], const float* __restrict__ vb,
                                      const ull (&w0)[16], const ull (&w1)[16]) {
#pragma unroll
    for (int c = 0; c < NC4; c++) {
#pragma unroll
        for (int b = 0; b < NBH; b++) {
            double2 v = *reinterpret_cast<const double2*>(vb + b * BSTR + c * 4);
            ull vx = d2l(v.x), vy = d2l(v.y);
            acc[0][b] = ffma2(vx, w0[2 * c],     acc[0][b]);
            acc[0][b] = ffma2(vy, w0[2 * c + 1], acc[0][b]);
            acc[1][b] = ffma2(vx, w1[2 * c],     acc[1][b]);
            acc[1][b] = ffma2(vy, w1[2 * c + 1], acc[1][b]);
        }
    }
}

__global__ void __launch_bounds__(256, 1)
lstm_fused_kernel(const float* __restrict__ x,
                  const float* __restrict__ Wih0, const float* __restrict__ Whh0,
                  const float* __restrict__ bih0, const float* __restrict__ bhh0,
                  const float* __restrict__ Wih1, const float* __restrict__ Whh1,
                  const float* __restrict__ bih1, const float* __restrict__ bhh1,
                  const float* __restrict__ Wc1,  const float* __restrict__ bc1,
                  const float* __restrict__ Wc2,  const float* __restrict__ bc2,
                  float* __restrict__ out) {
    __shared__ Smem s;
    const int tid  = threadIdx.x;
    const int half = tid >> 7;
    const int lt   = tid & 127;
    const int grp  = lt >> 6;
    const int gl   = lt & 63;
    const bool is_l0 = ((grp ^ half) == 0);   // SMSP-balanced layer map
    const int bbase = blockIdx.x * BPB + half * NBH;

    // ---- zero state (xs, h0, h1 contiguous at struct start) ----
    {
        float* zp = reinterpret_cast<float*>(&s);
        const int zn = (int)((sizeof(s.xs) + sizeof(s.h0) + sizeof(s.h1)) / 4);
        for (int i = tid; i < zn; i += 256) zp[i] = 0.0f;
    }
    // ---- stage x(0) (batch-clamped for tail blocks) ----
    for (int i = tid; i < 2 * NBH * II; i += 256) {
        int hf = i / (NBH * II), r = i % (NBH * II), b = r / II, k = r % II;
        int gb = blockIdx.x * BPB + hf * NBH + b;
        if (gb > BB - 1) gb = BB - 1;
        s.xs[hf][0][b][k] = x[(size_t)gb * TT * II + k];
    }

    // ---- register-resident weights: rows (gl, gl+64) of ONE layer ----
    ull wA[2][16], wB[2][16];
    ull biasA, biasB;
    if (is_l0) {
#pragma unroll
        for (int i = 0; i < 2; i++) {
            int r = gl + i * 64;
#pragma unroll
            for (int p = 0; p < 8; p++) {
                float lo = (2 * p     < II) ? Wih0[r * II + 2 * p]     : 0.0f;
                float hi = (2 * p + 1 < II) ? Wih0[r * II + 2 * p + 1] : 0.0f;
                wA[i][p] = packf2(lo, hi);
            }
#pragma unroll
            for (int p = 8; p < 16; p++) wA[i][p] = 0;
#pragma unroll
            for (int p = 0; p < 16; p++)
                wB[i][p] = packf2(Whh0[r * HH + 2 * p], Whh0[r * HH + 2 * p + 1]);
        }
        biasA = packf2(bih0[gl] + bhh0[gl], 0.0f);
        biasB = packf2(bih0[gl + 64] + bhh0[gl + 64], 0.0f);
    } else {
#pragma unroll
        for (int i = 0; i < 2; i++) {
            int r = gl + i * 64;
#pragma unroll
            for (int p = 0; p < 16; p++) {
                wA[i][p] = packf2(Wih1[r * HH + 2 * p], Wih1[r * HH + 2 * p + 1]);
                wB[i][p] = packf2(Whh1[r * HH + 2 * p], Whh1[r * HH + 2 * p + 1]);
            }
        }
        biasA = packf2(bih1[gl] + bhh1[gl], 0.0f);
        biasB = packf2(bih1[gl + 64] + bhh1[gl + 64], 0.0f);
    }

    const int eu  = gl & 31;
    const int ebb = (gl >> 5) * 4;
    float cst[4] = {0.f, 0.f, 0.f, 0.f};

    float* gs = s.gates[half][grp];

    // ---- x staging slots (L0 threads) ----
    const int pb0 = gl >> 4,        pk0 = gl & 15;
    const int pb1 = (gl + 64) >> 4, pk1 = (gl + 64) & 15;
    const bool pv0 = (pb0 < NBH) && (pk0 < II);
    const bool pv1 = (pb1 < NBH) && (pk1 < II);
    int cb0 = bbase + pb0; if (cb0 > BB - 1) cb0 = BB - 1;
    int cb1 = bbase + pb1; if (cb1 > BB - 1) cb1 = BB - 1;
    const float* xc0 = x + (size_t)cb0 * TT * II + pk0;
    const float* xc1 = x + (size_t)cb1 * TT * II + pk1;

    // barrier ids: idA[slot] = 1+4h+slot, idB[slot] = 3+4h+slot, GBAR = 9+2h+grp
    const int idA0 = 1 + 4 * half;
    const int idB0 = 3 + 4 * half;
    const int idG  = 9 + 2 * half + grp;

    __syncthreads();

#define ARRV(id) asm volatile("bar.arrive %0, 128;" :: "r"(id) : "memory")
#define WAIT(id) asm volatile("bar.sync %0, 128;"   :: "r"(id) : "memory")
#define GBAR()   asm volatile("bar.sync %0, 64;"    :: "r"(idG) : "memory")

    for (int t = 0; t <= TT; t++) {
        const int par = t & 1;
        if (is_l0) {
            if (t < TT) {
                GBAR();   // intra-L0: h0(t-1) slot par / xs(t) visible
                float xn0 = 0.f, xn1 = 0.f;
                if (t + 1 < TT) {
                    if (pv0) xn0 = xc0[(size_t)(t + 1) * II];
                    if (pv1) xn1 = xc1[(size_t)(t + 1) * II];
                }
                // GEMM0: gates0(t) = b0 + Wx0*x(t) + Wh0*h0(t-1)
                const float* xsv = &s.xs[half][par][0][0];
                const float* h0v = &s.h0[half][par][0][0];   // h0(t-1) in slot par
                ull acc[2][NBH];
#pragma unroll
                for (int b = 0; b < NBH; b++) { acc[0][b] = biasA; acc[1][b] = biasB; }
                gemm2<4, 16>(acc, xsv, wA[0], wA[1]);
                gemm2<8, HH>(acc, h0v, wB[0], wB[1]);
#pragma unroll
                for (int b = 0; b < NBH; b++) {
                    gs[gl * GSTR + b]        = hadd2(acc[0][b]);
                    gs[(gl + 64) * GSTR + b] = hadd2(acc[1][b]);
                }
                GBAR();                              // gates0 ready
                if (t >= 2) WAIT(idB0 + (par ^ 1));  // L1 done reading slot par^1
                // EW layer0: writes h0(t) into slot par^1
#pragma unroll
                for (int j = 0; j < 4; j++) {
                    int b = ebb + j;
                    if (b < NBH) {
                        float gi = gs[(eu)      * GSTR + b];
                        float gf = gs[(eu + 32) * GSTR + b];
                        float gg = gs[(eu + 64) * GSTR + b];
                        float go = gs[(eu + 96) * GSTR + b];
                        float ig = sigf(gi), fg = sigf(gf);
                        float gv = tanhap(gg), og = sigf(go);
                        cst[j] = fmaf(fg, cst[j], ig * gv);
                        s.h0[half][par ^ 1][b][eu] = og * tanhap(cst[j]);
                    }
                }
                ARRV(idA0 + (par ^ 1));              // h0(t) published (slot par^1)
                if (t + 1 < TT) {
                    if (pv0) s.xs[half][par ^ 1][pb0][pk0] = xn0;
                    if (pv1) s.xs[half][par ^ 1][pb1][pk1] = xn1;
                }
            }
        } else {
            if (t > 0) {
                // private part first: b1 + Whh1*h1(t-2)
                const float* h1v = &s.h1[half][0][0];
                ull acc[2][NBH];
#pragma unroll
                for (int b = 0; b < NBH; b++) { acc[0][b] = biasA; acc[1][b] = biasB; }
                gemm2<8, HH>(acc, h1v, wB[0], wB[1]);
                WAIT(idA0 + par);                    // h0(t-1) ready in slot par
                const float* h0v = &s.h0[half][par][0][0];
                gemm2<8, HH>(acc, h0v, wA[0], wA[1]);
#pragma unroll
                for (int b = 0; b < NBH; b++) {
                    gs[gl * GSTR + b]        = hadd2(acc[0][b]);
                    gs[(gl + 64) * GSTR + b] = hadd2(acc[1][b]);
                }
                ARRV(idB0 + par);                    // slot par consumed
                GBAR();                              // gates1 ready
                // EW layer1: writes h1(t-1)
#pragma unroll
                for (int j = 0; j < 4; j++) {
                    int b = ebb + j;
                    if (b < NBH) {
                        float gi = gs[(eu)      * GSTR + b];
                        float gf = gs[(eu + 32) * GSTR + b];
                        float gg = gs[(eu + 64) * GSTR + b];
                        float go = gs[(eu + 96) * GSTR + b];
                        float ig = sigf(gi), fg = sigf(gf);
                        float gv = tanhap(gg), og = sigf(go);
                        cst[j] = fmaf(fg, cst[j], ig * gv);
                        s.h1[half][b][eu] = og * tanhap(cst[j]);
                    }
                }
                GBAR();                              // h1 visible in-group
            }
        }
    }
    __syncthreads();

    // ---- classifier head ----
    {
        int hj = lt & 31, hb = lt >> 5;
        float* hs = s.gates[half][0];
#pragma unroll
        for (int s2 = 0; s2 < 2; s2++) {
            int b = hb + 4 * s2;
            if (b < NBH) {
                float a = bc1[hj];
#pragma unroll
                for (int k = 0; k < HH; k++)
                    a = fmaf(s.h1[half][b][k], Wc1[hj * HH + k], a);
                hs[hj * GSTR + b] = fmaxf(a, 0.0f);
            }
        }
    }
    __syncthreads();
    if (lt < NBH * NC) {
        int b = lt / NC, c = lt - b * NC;
        if (bbase + b < BB) {
            float* hs = s.gates[half][0];
            float o = bc2[c];
#pragma unroll
            for (int j = 0; j < HH; j++)
                o = fmaf(hs[j * GSTR + b], Wc2[c * HH + j], o);
            out[(size_t)(bbase + b) * NC + c] = o;
        }
    }
#undef ARRV
#undef WAIT
#undef GBAR
}

extern "C" void kernel_launch(void* const* d_in, const int* in_sizes, int n_in,
                              void* d_out, int out_size) {
    const float* x    = (const float*)d_in[0];
    const float* Wih0 = (const float*)d_in[1];
    const float* Whh0 = (const float*)d_in[2];
    const float* bih0 = (const float*)d_in[3];
    const float* bhh0 = (const float*)d_in[4];
    const float* Wih1 = (const float*)d_in[5];
    const float* Whh1 = (const float*)d_in[6];
    const float* bih1 = (const float*)d_in[7];
    const float* bhh1 = (const float*)d_in[8];
    const float* Wc1  = (const float*)d_in[9];
    const float* bc1  = (const float*)d_in[10];
    const float* Wc2  = (const float*)d_in[11];
    const float* bc2  = (const float*)d_in[12];
    float* out = (float*)d_out;

    lstm_fused_kernel<<<GRIDN, 256>>>(
        x, Wih0, Whh0, bih0, bhh0, Wih1, Whh1, bih1, bhh1,
        Wc1, bc1, Wc2, bc2, out);
}